// round 10
// baseline (speedup 1.0000x reference)
#include <cuda_runtime.h>
#include <math.h>
#include <stdint.h>

#define S_STEPS 128
#define NNODE   32
#define DIM     300
#define NREL    4
#define NEDGE   64
#define VOUT    50000

// ---------------- scratch (device globals; no allocs allowed) ----------------
__device__ __align__(16) float g_GX[S_STEPS * NNODE * DIM];   // gathered features [s][n][d]
__device__ __align__(16) float g_Y [S_STEPS * NREL * DIM];    // weighted node sums [s][r][d]
__device__ __align__(16) float g_A [S_STEPS * DIM];           // gxflat @ Wg
__device__ __align__(16) float g_P0[S_STEPS * DIM];           // proposed row 0
__device__ __align__(16) float g_X1[S_STEPS * DIM];           // leaky_relu(new[0]) per step
__device__ float g_sub[S_STEPS];                              // logsumexp per row

// ---------------- helpers ----------------
__device__ __forceinline__ uint32_t smem_u32(const void* p) {
    uint32_t a;
    asm("{ .reg .u64 t; cvta.to.shared.u64 t, %1; cvt.u32.u64 %0, t; }" : "=r"(a) : "l"(p));
    return a;
}
__device__ __forceinline__ void st_cluster_f32(uint32_t saddr, uint32_t rank, float v) {
    uint32_t remote;
    asm volatile("mapa.shared::cluster.u32 %0, %1, %2;" : "=r"(remote) : "r"(saddr), "r"(rank));
    asm volatile("st.shared::cluster.b32 [%0], %1;" :: "r"(remote), "r"(__float_as_int(v)) : "memory");
}

// ---------------- K1: gather grapharea features ----------------
__global__ void k_gather(const int* __restrict__ xind, const float* __restrict__ X) {
    int s = blockIdx.x;
    __shared__ int idx[NNODE];
    int tid = threadIdx.x;
    if (tid < NNODE) idx[tid] = xind[s * NNODE + tid];
    __syncthreads();
    const float4* Xv = (const float4*)X;                 // 75 float4 per row
    float4* Gv = (float4*)(g_GX + s * (NNODE * DIM));
    for (int f = tid; f < NNODE * (DIM / 4); f += blockDim.x) {
        int n = f / (DIM / 4), j = f % (DIM / 4);
        Gv[f] = Xv[(size_t)idx[n] * (DIM / 4) + j];
    }
}

// ---------------- K2: per-step graph prep -> Y weighted sums ----------------
__global__ void k_prep(const int* __restrict__ eidx, const int* __restrict__ etyp) {
    int s = blockIdx.x;
    __shared__ int ssrc[NEDGE], sdst[NEDGE], styp[NEDGE];
    __shared__ int degc[NREL][NNODE];
    __shared__ float dis[NREL][NNODE];
    __shared__ float w[NREL][NNODE];
    int tid = threadIdx.x;                               // 128 threads
    if (tid < NEDGE) {
        ssrc[tid] = eidx[s * (2 * NEDGE) + tid];
        sdst[tid] = eidx[s * (2 * NEDGE) + NEDGE + tid];
        styp[tid] = etyp[s * NEDGE + tid];
    }
    if (tid < NREL * NNODE) ((int*)degc)[tid] = 0;
    __syncthreads();
    if (tid < NEDGE) atomicAdd(&degc[styp[tid]][sdst[tid]], 1);
    __syncthreads();
    if (tid < NREL * NNODE) {
        int r = tid >> 5, n = tid & 31;
        dis[r][n] = rsqrtf((float)degc[r][n] + 1.0f);
        ((float*)w)[tid] = 0.0f;
    }
    __syncthreads();
    if (tid < NEDGE && sdst[tid] == 0) {
        int r = styp[tid], sr = ssrc[tid];
        atomicAdd(&w[r][sr], dis[r][sr] * dis[r][0]);
    }
    __syncthreads();
    if (tid < NREL) w[tid][0] += dis[tid][0] * dis[tid][0];   // self-loop on node 0
    __syncthreads();
    const float* gx = g_GX + s * (NNODE * DIM);
    for (int r = 0; r < NREL; r++) {
        for (int d = tid; d < DIM; d += blockDim.x) {
            float acc = 0.0f;
            #pragma unroll 1
            for (int n = 0; n < NNODE; n++) {
                float ww = w[r][n];
                if (ww != 0.0f) acc = fmaf(ww, gx[n * DIM + d], acc);
            }
            g_Y[s * (NREL * DIM) + r * DIM + d] = acc;
        }
    }
}

// ---------------- K3: zero accumulators + senses ----------------
__global__ void k_zero(float* __restrict__ senses) {
    int i = blockIdx.x * blockDim.x + threadIdx.x;
    if (i < S_STEPS * DIM) { g_A[i] = 0.0f; g_P0[i] = 0.0f; }
    if (i < S_STEPS) senses[i] = 0.0f;
}

// ---------------- K4: A = GXflat[128,9600] @ Wg[9600,300] (k-split, atomic) ----------------
__global__ void k_gemmA(const float* __restrict__ Wg) {
    const int c0 = blockIdx.x * 64;          // 5 col tiles (0..4)
    const int kbase = blockIdx.y * 320;      // 30 k splits
    __shared__ float xs[16][128];
    __shared__ float ws[16][64];
    int tid = threadIdx.x;
    int tx = tid & 15, ty = tid >> 4;
    float acc[8][4];
    #pragma unroll
    for (int i = 0; i < 8; i++)
        #pragma unroll
        for (int j = 0; j < 4; j++) acc[i][j] = 0.0f;
    int lt = tid >> 1, lh = (tid & 1) * 8;
    int wc = tid & 63, wq = (tid >> 6) * 4;
    for (int kb = 0; kb < 320; kb += 16) {
        const float* gsrc = g_GX + lt * 9600 + kbase + kb + lh;
        #pragma unroll
        for (int j = 0; j < 8; j++) xs[lh + j][lt] = gsrc[j];
        #pragma unroll
        for (int j = 0; j < 4; j++) {
            int kk = wq + j;
            ws[kk][wc] = (c0 + wc < DIM) ? Wg[(kbase + kb + kk) * DIM + c0 + wc] : 0.0f;
        }
        __syncthreads();
        #pragma unroll
        for (int kk = 0; kk < 16; kk++) {
            float4 a0 = *(const float4*)&xs[kk][ty * 8];
            float4 a1 = *(const float4*)&xs[kk][ty * 8 + 4];
            float4 b  = *(const float4*)&ws[kk][tx * 4];
            float av[8] = {a0.x,a0.y,a0.z,a0.w,a1.x,a1.y,a1.z,a1.w};
            float bv[4] = {b.x,b.y,b.z,b.w};
            #pragma unroll
            for (int i = 0; i < 8; i++)
                #pragma unroll
                for (int j = 0; j < 4; j++) acc[i][j] = fmaf(av[i], bv[j], acc[i][j]);
        }
        __syncthreads();
    }
    #pragma unroll
    for (int i = 0; i < 8; i++) {
        int row = ty * 8 + i;
        #pragma unroll
        for (int j = 0; j < 4; j++) {
            int c = c0 + tx * 4 + j;
            if (c < DIM) atomicAdd(&g_A[row * DIM + c], acc[i][j]);
        }
    }
}

// ---------------- K5: P0 = sum_r Y_r @ conv_W[r] + GX0 @ W0 (k-split, atomic) ----------------
__global__ void k_gemmP0(const float* __restrict__ convW, const float* __restrict__ W0) {
    const int c0 = blockIdx.x * 64;      // 5 col tiles
    const int kbase = blockIdx.y * 100;  // 3 k splits
    const int op = blockIdx.z;           // 0..4
    const float* Ab; int lda; const float* Bb;
    if (op < 4) { Ab = g_Y + op * DIM; lda = NREL * DIM; Bb = convW + op * DIM * DIM; }
    else        { Ab = g_GX;           lda = NNODE * DIM; Bb = W0; }
    __shared__ float xs[20][128];
    __shared__ float ws[20][64];
    int tid = threadIdx.x;
    int tx = tid & 15, ty = tid >> 4;
    float acc[8][4];
    #pragma unroll
    for (int i = 0; i < 8; i++)
        #pragma unroll
        for (int j = 0; j < 4; j++) acc[i][j] = 0.0f;
    int lt = tid >> 1, lh = (tid & 1) * 10;
    int wc = tid & 63, wq = (tid >> 6) * 5;
    for (int kb = 0; kb < 100; kb += 20) {
        const float* asrc = Ab + lt * lda + kbase + kb + lh;
        #pragma unroll
        for (int j = 0; j < 10; j++) xs[lh + j][lt] = asrc[j];
        #pragma unroll
        for (int j = 0; j < 5; j++) {
            int kk = wq + j;
            ws[kk][wc] = (c0 + wc < DIM) ? Bb[(kbase + kb + kk) * DIM + c0 + wc] : 0.0f;
        }
        __syncthreads();
        #pragma unroll
        for (int kk = 0; kk < 20; kk++) {
            float4 a0 = *(const float4*)&xs[kk][ty * 8];
            float4 a1 = *(const float4*)&xs[kk][ty * 8 + 4];
            float4 b  = *(const float4*)&ws[kk][tx * 4];
            float av[8] = {a0.x,a0.y,a0.z,a0.w,a1.x,a1.y,a1.z,a1.w};
            float bv[4] = {b.x,b.y,b.z,b.w};
            #pragma unroll
            for (int i = 0; i < 8; i++)
                #pragma unroll
                for (int j = 0; j < 4; j++) acc[i][j] = fmaf(av[i], bv[j], acc[i][j]);
        }
        __syncthreads();
    }
    #pragma unroll
    for (int i = 0; i < 8; i++) {
        int row = ty * 8 + i;
        #pragma unroll
        for (int j = 0; j < 4; j++) {
            int c = c0 + tx * 4 + j;
            if (c < DIM) atomicAdd(&g_P0[row * DIM + c], acc[i][j]);
        }
    }
}

// ---------------- K6: sequential gate recurrence (4-CTA cluster, Ug in registers) ----------------
__global__ void __cluster_dims__(4, 1, 1) k_recur(const float* __restrict__ Ug) {
    __shared__ __align__(16) float mbuf[2][304];   // double-buffered full m (padded 300->304)
    int tid = threadIdx.x;                         // 320 threads, 300 active
    uint32_t rank;
    asm("mov.u32 %0, %%cluster_ctarank;" : "=r"(rank));
    bool act = tid < 300;
    int g = tid >> 2, s = tid & 3;
    int e = (int)rank * 75 + g;                    // output index this group owns
    float ug[76];
    if (act) {
        #pragma unroll
        for (int j = 0; j < 76; j++) {
            int d = s * 76 + j;
            ug[j] = (d < DIM) ? __ldg(&Ug[d * DIM + e]) : 0.0f;
        }
    }
    for (int j = tid; j < 2 * 304; j += blockDim.x) ((float*)mbuf)[j] = 0.0f;
    __syncthreads();
    asm volatile("barrier.cluster.arrive.aligned;" ::: "memory");
    asm volatile("barrier.cluster.wait.aligned;" ::: "memory");
    unsigned mask = __ballot_sync(0xFFFFFFFFu, act);

    for (int t = 0; t < S_STEPS; t++) {
        int p = t & 1;
        if (act) {
            const float4* mv = reinterpret_cast<const float4*>(&mbuf[p][s * 76]);
            float acc = 0.0f;
            #pragma unroll
            for (int q = 0; q < 19; q++) {
                float4 v = mv[q];
                acc = fmaf(ug[4 * q + 0], v.x, acc);
                acc = fmaf(ug[4 * q + 1], v.y, acc);
                acc = fmaf(ug[4 * q + 2], v.z, acc);
                acc = fmaf(ug[4 * q + 3], v.w, acc);
            }
            acc += __shfl_xor_sync(mask, acc, 1);
            acc += __shfl_xor_sync(mask, acc, 2);
            float a   = g_A [t * DIM + e];
            float p0v = g_P0[t * DIM + e];
            float mold = mbuf[p][e];
            float u = 1.0f / (1.0f + __expf(-(acc + a)));
            float mn = fmaf(u, p0v - mold, mold);       // u*p0 + (1-u)*mold
            uint32_t laddr = smem_u32(&mbuf[1 - p][e]);
            st_cluster_f32(laddr, (uint32_t)s, mn);      // lane s delivers to CTA rank s
            if (s == 0) g_X1[t * DIM + e] = (mn >= 0.0f) ? mn : 0.01f * mn;
        }
        asm volatile("barrier.cluster.arrive.aligned;" ::: "memory");
        asm volatile("barrier.cluster.wait.aligned;" ::: "memory");
    }
}

// ---------------- K7: logits = X1[128,300] @ lin_w[50000,300]^T + b ----------------
__global__ void k_logits(const float* __restrict__ lin_w, const float* __restrict__ lin_b,
                         float* __restrict__ out) {
    const int v0 = blockIdx.x * 64;
    __shared__ float xs[20][128];
    __shared__ float ws[20][68];   // padded to break STS bank conflicts
    int tid = threadIdx.x;
    int tx = tid & 15, ty = tid >> 4;
    float acc[8][4];
    #pragma unroll
    for (int i = 0; i < 8; i++)
        #pragma unroll
        for (int j = 0; j < 4; j++) acc[i][j] = 0.0f;
    int lt = tid >> 1, lh = (tid & 1) * 10;
    int wc = tid >> 2, wq = (tid & 3) * 5;
    int vthis = v0 + wc;
    for (int kb = 0; kb < DIM; kb += 20) {
        const float* xsrc = g_X1 + lt * DIM + kb + lh;
        #pragma unroll
        for (int j = 0; j < 10; j++) xs[lh + j][lt] = xsrc[j];
        const float* wsrc = lin_w + (size_t)vthis * DIM + kb + wq;
        #pragma unroll
        for (int j = 0; j < 5; j++) ws[wq + j][wc] = (vthis < VOUT) ? wsrc[j] : 0.0f;
        __syncthreads();
        #pragma unroll
        for (int kk = 0; kk < 20; kk++) {
            float4 a0 = *(const float4*)&xs[kk][ty * 8];
            float4 a1 = *(const float4*)&xs[kk][ty * 8 + 4];
            float4 b  = *(const float4*)&ws[kk][tx * 4];
            float av[8] = {a0.x,a0.y,a0.z,a0.w,a1.x,a1.y,a1.z,a1.w};
            float bv[4] = {b.x,b.y,b.z,b.w};
            #pragma unroll
            for (int i = 0; i < 8; i++)
                #pragma unroll
                for (int j = 0; j < 4; j++) acc[i][j] = fmaf(av[i], bv[j], acc[i][j]);
        }
        __syncthreads();
    }
    int v = v0 + tx * 4;
    float bb[4];
    #pragma unroll
    for (int j = 0; j < 4; j++) bb[j] = (v + j < VOUT) ? lin_b[v + j] : 0.0f;
    #pragma unroll
    for (int i = 0; i < 8; i++) {
        int row = ty * 8 + i;
        size_t base = (size_t)row * VOUT + v;
        if (v + 3 < VOUT) {
            float4 r;
            r.x = acc[i][0] + bb[0]; r.y = acc[i][1] + bb[1];
            r.z = acc[i][2] + bb[2]; r.w = acc[i][3] + bb[3];
            *(float4*)(out + base) = r;
        } else {
            #pragma unroll
            for (int j = 0; j < 4; j++)
                if (v + j < VOUT) out[base + j] = acc[i][j] + bb[j];
        }
    }
}

// ---------------- K8: per-row online logsumexp ----------------
__global__ void k_lse(const float* __restrict__ out) {
    int t = blockIdx.x;
    const float4* row = (const float4*)(out + (size_t)t * VOUT);
    float m = -1e30f, ssum = 0.0f;
    for (int i = threadIdx.x; i < VOUT / 4; i += blockDim.x) {
        float4 v = row[i];
        float lm = fmaxf(fmaxf(v.x, v.y), fmaxf(v.z, v.w));
        if (lm > m) { ssum *= __expf(m - lm); m = lm; }
        ssum += __expf(v.x - m) + __expf(v.y - m) + __expf(v.z - m) + __expf(v.w - m);
    }
    __shared__ float sm[256], ss[256];
    int tid = threadIdx.x;
    sm[tid] = m; ss[tid] = ssum;
    __syncthreads();
    for (int k = 128; k > 0; k >>= 1) {
        if (tid < k) {
            float m2 = sm[tid + k], s2 = ss[tid + k];
            float M = fmaxf(sm[tid], m2);
            ss[tid] = ss[tid] * __expf(sm[tid] - M) + s2 * __expf(m2 - M);
            sm[tid] = M;
        }
        __syncthreads();
    }
    if (tid == 0) g_sub[t] = sm[0] + logf(ss[0]);
}

// ---------------- K9: finalize log_softmax ----------------
__global__ void k_final(float* __restrict__ out) {
    const size_t total4 = (size_t)S_STEPS * VOUT / 4;
    size_t stride = (size_t)gridDim.x * blockDim.x;
    for (size_t i = blockIdx.x * (size_t)blockDim.x + threadIdx.x; i < total4; i += stride) {
        int t = (int)(i / (VOUT / 4));
        float sb = g_sub[t];
        float4 v = ((float4*)out)[i];
        v.x -= sb; v.y -= sb; v.z -= sb; v.w -= sb;
        ((float4*)out)[i] = v;
    }
}

// ---------------- launch ----------------
extern "C" void kernel_launch(void* const* d_in, const int* in_sizes, int n_in,
                              void* d_out, int out_size) {
    (void)in_sizes; (void)n_in; (void)out_size;
    const int*   xind  = (const int*)d_in[0];
    const int*   eidx  = (const int*)d_in[1];
    const int*   etyp  = (const int*)d_in[2];
    const float* X     = (const float*)d_in[3];
    const float* convW = (const float*)d_in[4];
    const float* W0    = (const float*)d_in[5];
    const float* Wg    = (const float*)d_in[6];
    const float* Ug    = (const float*)d_in[7];
    const float* lw    = (const float*)d_in[8];
    const float* lb    = (const float*)d_in[9];
    float* out = (float*)d_out;

    k_gather<<<S_STEPS, 256>>>(xind, X);
    k_prep<<<S_STEPS, 128>>>(eidx, etyp);
    k_zero<<<(S_STEPS * DIM + 255) / 256, 256>>>(out + (size_t)S_STEPS * VOUT);
    k_gemmA<<<dim3(5, 30), 256>>>(Wg);
    k_gemmP0<<<dim3(5, 3, 5), 256>>>(convW, W0);
    k_recur<<<4, 320>>>(Ug);
    k_logits<<<(VOUT + 63) / 64, 256>>>(lw, lb, out);
    k_lse<<<S_STEPS, 256>>>(out);
    k_final<<<1600, 256>>>(out);
}

// round 13
// speedup vs baseline: 1.3486x; 1.3486x over previous
#include <cuda_runtime.h>
#include <math.h>
#include <stdint.h>

#define S_STEPS 128
#define NNODE   32
#define DIM     300
#define NREL    4
#define NEDGE   64
#define VOUT    50000

#define KS_GX 1200   // ksteps for GX (K=9600)
#define KS_X1 40     // ksteps for X1 (K padded 300->320)

// ---------------- scratch (device globals; no allocs allowed) ----------------
__device__ __align__(16) float g_GX[S_STEPS * NNODE * DIM];   // gathered features [s][n*d]
__device__ __align__(16) float g_Y [S_STEPS * NREL * DIM];    // weighted node sums [s][r][d]
__device__ __align__(16) float g_A [S_STEPS * DIM];           // gxflat @ Wg
__device__ __align__(16) float g_P0[S_STEPS * DIM];           // proposed row 0
__device__ __align__(16) float g_X1[S_STEPS * DIM];           // leaky_relu(new[0]) per step
__device__ float g_sub[S_STEPS];                              // logsumexp per row
// fragment-order A operands for mma (float4 per lane per (mtile,kstep))
__device__ __align__(16) float g_FGX[8 * KS_GX * 32 * 4];     // 4.7MB
__device__ __align__(16) float g_FA1[8 * KS_X1 * 32 * 4];     // 160KB

// ---------------- helpers ----------------
__device__ __forceinline__ uint32_t smem_u32(const void* p) {
    uint32_t a;
    asm("{ .reg .u64 t; cvta.to.shared.u64 t, %1; cvt.u32.u64 %0, t; }" : "=r"(a) : "l"(p));
    return a;
}
__device__ __forceinline__ void st_cluster_f32(uint32_t saddr, uint32_t rank, float v) {
    uint32_t remote;
    asm volatile("mapa.shared::cluster.u32 %0, %1, %2;" : "=r"(remote) : "r"(saddr), "r"(rank));
    asm volatile("st.shared::cluster.b32 [%0], %1;" :: "r"(remote), "r"(__float_as_int(v)) : "memory");
}
// D += A(16x8) * B(8x8), tf32 inputs (raw fp32 bits -> truncated), fp32 accum
__device__ __forceinline__ void mma8(float* c, const float4& a, float b0, float b1) {
    asm volatile(
        "mma.sync.aligned.m16n8k8.row.col.f32.tf32.tf32.f32 "
        "{%0,%1,%2,%3}, {%4,%5,%6,%7}, {%8,%9}, {%0,%1,%2,%3};"
        : "+f"(c[0]), "+f"(c[1]), "+f"(c[2]), "+f"(c[3])
        : "r"(__float_as_uint(a.x)), "r"(__float_as_uint(a.y)),
          "r"(__float_as_uint(a.z)), "r"(__float_as_uint(a.w)),
          "r"(__float_as_uint(b0)), "r"(__float_as_uint(b1)));
}

// ---------------- K1: gather grapharea features ----------------
__global__ void k_gather(const int* __restrict__ xind, const float* __restrict__ X) {
    int s = blockIdx.x;
    __shared__ int idx[NNODE];
    int tid = threadIdx.x;
    if (tid < NNODE) idx[tid] = xind[s * NNODE + tid];
    __syncthreads();
    const float4* Xv = (const float4*)X;                 // 75 float4 per row
    float4* Gv = (float4*)(g_GX + s * (NNODE * DIM));
    for (int f = tid; f < NNODE * (DIM / 4); f += blockDim.x) {
        int n = f / (DIM / 4), j = f % (DIM / 4);
        Gv[f] = Xv[(size_t)idx[n] * (DIM / 4) + j];
    }
}

// ---------------- K2: per-step graph prep -> Y weighted sums ----------------
__global__ void k_prep(const int* __restrict__ eidx, const int* __restrict__ etyp) {
    int s = blockIdx.x;
    __shared__ int ssrc[NEDGE], sdst[NEDGE], styp[NEDGE];
    __shared__ int degc[NREL][NNODE];
    __shared__ float dis[NREL][NNODE];
    __shared__ float w[NREL][NNODE];
    int tid = threadIdx.x;                               // 128 threads
    if (tid < NEDGE) {
        ssrc[tid] = eidx[s * (2 * NEDGE) + tid];
        sdst[tid] = eidx[s * (2 * NEDGE) + NEDGE + tid];
        styp[tid] = etyp[s * NEDGE + tid];
    }
    if (tid < NREL * NNODE) ((int*)degc)[tid] = 0;
    __syncthreads();
    if (tid < NEDGE) atomicAdd(&degc[styp[tid]][sdst[tid]], 1);
    __syncthreads();
    if (tid < NREL * NNODE) {
        int r = tid >> 5, n = tid & 31;
        dis[r][n] = rsqrtf((float)degc[r][n] + 1.0f);
        ((float*)w)[tid] = 0.0f;
    }
    __syncthreads();
    if (tid < NEDGE && sdst[tid] == 0) {
        int r = styp[tid], sr = ssrc[tid];
        atomicAdd(&w[r][sr], dis[r][sr] * dis[r][0]);
    }
    __syncthreads();
    if (tid < NREL) w[tid][0] += dis[tid][0] * dis[tid][0];   // self-loop on node 0
    __syncthreads();
    const float* gx = g_GX + s * (NNODE * DIM);
    for (int r = 0; r < NREL; r++) {
        for (int d = tid; d < DIM; d += blockDim.x) {
            float acc = 0.0f;
            #pragma unroll 1
            for (int n = 0; n < NNODE; n++) {
                float ww = w[r][n];
                if (ww != 0.0f) acc = fmaf(ww, gx[n * DIM + d], acc);
            }
            g_Y[s * (NREL * DIM) + r * DIM + d] = acc;
        }
    }
}

// ---------------- K3: zero accumulators + senses ----------------
__global__ void k_zero(float* __restrict__ senses) {
    int i = blockIdx.x * blockDim.x + threadIdx.x;
    if (i < S_STEPS * DIM) { g_A[i] = 0.0f; g_P0[i] = 0.0f; }
    if (i < S_STEPS) senses[i] = 0.0f;
}

// ---------------- frag prep: swizzle A operand into mma fragment order ----------------
__device__ __forceinline__ void frag_core(const float* __restrict__ src, float* __restrict__ dst,
                                          int KS, int srcK, int validK) {
    int total = 8 * KS * 32;
    for (int idx = blockIdx.x * blockDim.x + threadIdx.x; idx < total;
         idx += gridDim.x * blockDim.x) {
        int lane = idx & 31;
        int ks   = (idx >> 5) % KS;
        int mt   = idx / (32 * KS);
        int g = lane >> 2, t4 = lane & 3;
        int r0 = mt * 16 + g, r1 = r0 + 8;
        int k0 = ks * 8 + t4;
        float4 v;
        v.x = (k0     < validK) ? src[r0 * srcK + k0]     : 0.0f;
        v.y = (k0     < validK) ? src[r1 * srcK + k0]     : 0.0f;
        v.z = (k0 + 4 < validK) ? src[r0 * srcK + k0 + 4] : 0.0f;
        v.w = (k0 + 4 < validK) ? src[r1 * srcK + k0 + 4] : 0.0f;
        *(float4*)(dst + (size_t)idx * 4) = v;
    }
}
__global__ void k_fragGX() { frag_core(g_GX, g_FGX, KS_GX, NNODE * DIM, NNODE * DIM); }
__global__ void k_fragX1() { frag_core(g_X1, g_FA1, KS_X1, DIM, DIM); }

// ---------------- K4: A = GXflat[128,9600] @ Wg[9600,300]  (tf32 mma, k-split atomic) ----------------
__global__ void k_gemmA_mma(const float* __restrict__ Wg) {
    const int n0  = blockIdx.x * 64;     // 5 col tiles (cols 0..319, guard <300)
    const int ksp = blockIdx.y;          // 30 k splits, 320 k each
    __shared__ float Bs[80][68];
    int tid = threadIdx.x;
    int w = tid >> 5, lane = tid & 31;
    int g = lane >> 2, t4 = lane & 3;
    int wm = w & 3, wn = w >> 2;
    float acc[2][4][4];
    #pragma unroll
    for (int a = 0; a < 2; a++)
        #pragma unroll
        for (int b = 0; b < 4; b++)
            #pragma unroll
            for (int c = 0; c < 4; c++) acc[a][b][c] = 0.0f;

    int nn  = tid & 63;
    int kk0 = (tid >> 6) * 20;
    bool nok = (n0 + nn) < DIM;
    for (int c = 0; c < 4; c++) {
        __syncthreads();
        {   // stage Wg[k][n] chunk: k in [ksp*320 + c*80, +80)
            int kbase = ksp * 320 + c * 80;
            #pragma unroll
            for (int j = 0; j < 20; j++) {
                int k = kbase + kk0 + j;
                Bs[kk0 + j][nn] = nok ? Wg[(size_t)k * DIM + n0 + nn] : 0.0f;
            }
        }
        __syncthreads();
        #pragma unroll
        for (int ks = 0; ks < 10; ks++) {
            int kstep = ksp * 40 + c * 10 + ks;
            float4 af[2];
            #pragma unroll
            for (int mt = 0; mt < 2; mt++) {
                int mtile = wm * 2 + mt;
                af[mt] = *(const float4*)(g_FGX + ((size_t)(mtile * KS_GX + kstep) * 32 + lane) * 4);
            }
            #pragma unroll
            for (int nt = 0; nt < 4; nt++) {
                int bn = wn * 32 + nt * 8 + g;
                float b0 = Bs[ks * 8 + t4][bn];
                float b1 = Bs[ks * 8 + t4 + 4][bn];
                #pragma unroll
                for (int mt = 0; mt < 2; mt++) mma8(acc[mt][nt], af[mt], b0, b1);
            }
        }
    }
    // epilogue: atomic accumulate (k-split)
    #pragma unroll
    for (int mt = 0; mt < 2; mt++) {
        int r0 = wm * 32 + mt * 16 + g, r1 = r0 + 8;
        #pragma unroll
        for (int nt = 0; nt < 4; nt++) {
            int col = n0 + wn * 32 + nt * 8 + t4 * 2;
            if (col < DIM) {
                atomicAdd(&g_A[r0 * DIM + col],     acc[mt][nt][0]);
                atomicAdd(&g_A[r0 * DIM + col + 1], acc[mt][nt][1]);
                atomicAdd(&g_A[r1 * DIM + col],     acc[mt][nt][2]);
                atomicAdd(&g_A[r1 * DIM + col + 1], acc[mt][nt][3]);
            }
        }
    }
}

// ---------------- K5: P0 = sum_r Y_r @ conv_W[r] + GX0 @ W0 (fp32 SIMT, small) ----------------
__global__ void k_gemmP0(const float* __restrict__ convW, const float* __restrict__ W0) {
    const int c0 = blockIdx.x * 64;      // 5 col tiles
    const int kbase = blockIdx.y * 100;  // 3 k splits
    const int op = blockIdx.z;           // 0..4
    const float* Ab; int lda; const float* Bb;
    if (op < 4) { Ab = g_Y + op * DIM; lda = NREL * DIM; Bb = convW + op * DIM * DIM; }
    else        { Ab = g_GX;           lda = NNODE * DIM; Bb = W0; }
    __shared__ float xs[20][128];
    __shared__ float ws[20][64];
    int tid = threadIdx.x;
    int tx = tid & 15, ty = tid >> 4;
    float acc[8][4];
    #pragma unroll
    for (int i = 0; i < 8; i++)
        #pragma unroll
        for (int j = 0; j < 4; j++) acc[i][j] = 0.0f;
    int lt = tid >> 1, lh = (tid & 1) * 10;
    int wc = tid & 63, wq = (tid >> 6) * 5;
    for (int kb = 0; kb < 100; kb += 20) {
        const float* asrc = Ab + lt * lda + kbase + kb + lh;
        #pragma unroll
        for (int j = 0; j < 10; j++) xs[lh + j][lt] = asrc[j];
        #pragma unroll
        for (int j = 0; j < 5; j++) {
            int kk = wq + j;
            ws[kk][wc] = (c0 + wc < DIM) ? Bb[(kbase + kb + kk) * DIM + c0 + wc] : 0.0f;
        }
        __syncthreads();
        #pragma unroll
        for (int kk = 0; kk < 20; kk++) {
            float4 a0 = *(const float4*)&xs[kk][ty * 8];
            float4 a1 = *(const float4*)&xs[kk][ty * 8 + 4];
            float4 b  = *(const float4*)&ws[kk][tx * 4];
            float av[8] = {a0.x,a0.y,a0.z,a0.w,a1.x,a1.y,a1.z,a1.w};
            float bv[4] = {b.x,b.y,b.z,b.w};
            #pragma unroll
            for (int i = 0; i < 8; i++)
                #pragma unroll
                for (int j = 0; j < 4; j++) acc[i][j] = fmaf(av[i], bv[j], acc[i][j]);
        }
        __syncthreads();
    }
    #pragma unroll
    for (int i = 0; i < 8; i++) {
        int row = ty * 8 + i;
        #pragma unroll
        for (int j = 0; j < 4; j++) {
            int c = c0 + tx * 4 + j;
            if (c < DIM) atomicAdd(&g_P0[row * DIM + c], acc[i][j]);
        }
    }
}

// ---------------- K6: sequential gate recurrence (4-CTA cluster, Ug in registers) ----------------
__global__ void __cluster_dims__(4, 1, 1) k_recur(const float* __restrict__ Ug) {
    __shared__ __align__(16) float mbuf[2][304];   // double-buffered full m
    int tid = threadIdx.x;                         // 320 threads, 300 active
    uint32_t rank;
    asm("mov.u32 %0, %%cluster_ctarank;" : "=r"(rank));
    bool act = tid < 300;
    int g = tid >> 2, s = tid & 3;
    int e = (int)rank * 75 + g;                    // output index this group owns
    float ug[76];
    if (act) {
        #pragma unroll
        for (int j = 0; j < 76; j++) {
            int d = s * 76 + j;
            ug[j] = (d < DIM) ? __ldg(&Ug[d * DIM + e]) : 0.0f;
        }
    }
    for (int j = tid; j < 2 * 304; j += blockDim.x) ((float*)mbuf)[j] = 0.0f;
    __syncthreads();
    asm volatile("barrier.cluster.arrive.aligned;" ::: "memory");
    asm volatile("barrier.cluster.wait.aligned;" ::: "memory");
    unsigned mask = __ballot_sync(0xFFFFFFFFu, act);

    float a_t = 0.0f, p_t = 0.0f;
    if (act) { a_t = g_A[e]; p_t = g_P0[e]; }      // prefetch t=0

    for (int t = 0; t < S_STEPS; t++) {
        int p = t & 1;
        if (act) {
            const float4* mv = reinterpret_cast<const float4*>(&mbuf[p][s * 76]);
            float ac[4] = {0.0f, 0.0f, 0.0f, 0.0f};
            #pragma unroll
            for (int q = 0; q < 19; q++) {
                float4 v = mv[q];
                float partial = fmaf(ug[4 * q + 0], v.x,
                                fmaf(ug[4 * q + 1], v.y,
                                fmaf(ug[4 * q + 2], v.z,
                                     ug[4 * q + 3] * v.w)));
                ac[q & 3] += partial;
            }
            float acc = (ac[0] + ac[1]) + (ac[2] + ac[3]);
            acc += __shfl_xor_sync(mask, acc, 1);
            acc += __shfl_xor_sync(mask, acc, 2);
            float mold = mbuf[p][e];
            float u = 1.0f / (1.0f + __expf(-(acc + a_t)));
            float mn = fmaf(u, p_t - mold, mold);       // u*p0 + (1-u)*mold
            uint32_t laddr = smem_u32(&mbuf[1 - p][e]);
            st_cluster_f32(laddr, (uint32_t)s, mn);      // lane s delivers to CTA rank s
            if (s == 0) g_X1[t * DIM + e] = (mn >= 0.0f) ? mn : 0.01f * mn;
        }
        asm volatile("barrier.cluster.arrive.aligned;" ::: "memory");
        if (act && t + 1 < S_STEPS) {                   // prefetch into barrier window
            a_t = g_A [(t + 1) * DIM + e];
            p_t = g_P0[(t + 1) * DIM + e];
        }
        asm volatile("barrier.cluster.wait.aligned;" ::: "memory");
    }
}

// ---------------- K7: logits = X1[128,300] @ lin_w[50000,300]^T + b  (tf32 mma) ----------------
__global__ void k_logits_mma(const float* __restrict__ lin_w, const float* __restrict__ lin_b,
                             float* __restrict__ out) {
    const int v0 = blockIdx.x * 64;
    __shared__ float Bs[80][68];
    int tid = threadIdx.x;
    int w = tid >> 5, lane = tid & 31;
    int g = lane >> 2, t4 = lane & 3;
    int wm = w & 3, wn = w >> 2;
    float acc[2][4][4];
    #pragma unroll
    for (int a = 0; a < 2; a++)
        #pragma unroll
        for (int b = 0; b < 4; b++)
            #pragma unroll
            for (int c = 0; c < 4; c++) acc[a][b][c] = 0.0f;

    int nn = tid >> 2;                   // 0..63 (row of lin_w tile)
    int kq = (tid & 3) * 20;             // 0,20,40,60
    int vrow = v0 + nn;
    bool vok = vrow < VOUT;
    const float* wbase = lin_w + (size_t)vrow * DIM;

    for (int c = 0; c < 4; c++) {
        __syncthreads();
        {   // stage lin_w[v][k] chunk transposed: Bs[k - c*80][n]
            const float* wr = wbase + c * 80 + kq;
            if (c < 3) {
                #pragma unroll
                for (int j = 0; j < 20; j += 4) {
                    float4 x = vok ? *(const float4*)(wr + j) : make_float4(0.f, 0.f, 0.f, 0.f);
                    Bs[kq + j][nn] = x.x; Bs[kq + j + 1][nn] = x.y;
                    Bs[kq + j + 2][nn] = x.z; Bs[kq + j + 3][nn] = x.w;
                }
            } else {
                #pragma unroll
                for (int j = 0; j < 20; j++) {
                    int k = c * 80 + kq + j;
                    Bs[kq + j][nn] = (vok && k < DIM) ? wr[j] : 0.0f;
                }
            }
        }
        __syncthreads();
        #pragma unroll
        for (int ks = 0; ks < 10; ks++) {
            int kstep = c * 10 + ks;
            float4 af[2];
            #pragma unroll
            for (int mt = 0; mt < 2; mt++) {
                int mtile = wm * 2 + mt;
                af[mt] = *(const float4*)(g_FA1 + ((size_t)(mtile * KS_X1 + kstep) * 32 + lane) * 4);
            }
            #pragma unroll
            for (int nt = 0; nt < 4; nt++) {
                int bn = wn * 32 + nt * 8 + g;
                float b0 = Bs[ks * 8 + t4][bn];
                float b1 = Bs[ks * 8 + t4 + 4][bn];
                #pragma unroll
                for (int mt = 0; mt < 2; mt++) mma8(acc[mt][nt], af[mt], b0, b1);
            }
        }
    }
    // epilogue: + bias, store
    #pragma unroll
    for (int mt = 0; mt < 2; mt++) {
        int r0 = wm * 32 + mt * 16 + g, r1 = r0 + 8;
        #pragma unroll
        for (int nt = 0; nt < 4; nt++) {
            int vc = v0 + wn * 32 + nt * 8 + t4 * 2;
            if (vc < VOUT) {   // VOUT even, vc even -> vc+1 also valid
                float2 bb = *(const float2*)(lin_b + vc);
                float2 o0, o1;
                o0.x = acc[mt][nt][0] + bb.x; o0.y = acc[mt][nt][1] + bb.y;
                o1.x = acc[mt][nt][2] + bb.x; o1.y = acc[mt][nt][3] + bb.y;
                *(float2*)(out + (size_t)r0 * VOUT + vc) = o0;
                *(float2*)(out + (size_t)r1 * VOUT + vc) = o1;
            }
        }
    }
}

// ---------------- K8: per-row online logsumexp ----------------
__global__ void k_lse(const float* __restrict__ out) {
    int t = blockIdx.x;
    const float4* row = (const float4*)(out + (size_t)t * VOUT);
    float m = -1e30f, ssum = 0.0f;
    for (int i = threadIdx.x; i < VOUT / 4; i += blockDim.x) {
        float4 v = row[i];
        float lm = fmaxf(fmaxf(v.x, v.y), fmaxf(v.z, v.w));
        if (lm > m) { ssum *= __expf(m - lm); m = lm; }
        ssum += __expf(v.x - m) + __expf(v.y - m) + __expf(v.z - m) + __expf(v.w - m);
    }
    __shared__ float sm[256], ss[256];
    int tid = threadIdx.x;
    sm[tid] = m; ss[tid] = ssum;
    __syncthreads();
    for (int k = 128; k > 0; k >>= 1) {
        if (tid < k) {
            float m2 = sm[tid + k], s2 = ss[tid + k];
            float M = fmaxf(sm[tid], m2);
            ss[tid] = ss[tid] * __expf(sm[tid] - M) + s2 * __expf(m2 - M);
            sm[tid] = M;
        }
        __syncthreads();
    }
    if (tid == 0) g_sub[t] = sm[0] + logf(ss[0]);
}

// ---------------- K9: finalize log_softmax ----------------
__global__ void k_final(float* __restrict__ out) {
    const size_t total4 = (size_t)S_STEPS * VOUT / 4;
    size_t stride = (size_t)gridDim.x * blockDim.x;
    for (size_t i = blockIdx.x * (size_t)blockDim.x + threadIdx.x; i < total4; i += stride) {
        int t = (int)(i / (VOUT / 4));
        float sb = g_sub[t];
        float4 v = ((float4*)out)[i];
        v.x -= sb; v.y -= sb; v.z -= sb; v.w -= sb;
        ((float4*)out)[i] = v;
    }
}

// ---------------- launch ----------------
extern "C" void kernel_launch(void* const* d_in, const int* in_sizes, int n_in,
                              void* d_out, int out_size) {
    (void)in_sizes; (void)n_in; (void)out_size;
    const int*   xind  = (const int*)d_in[0];
    const int*   eidx  = (const int*)d_in[1];
    const int*   etyp  = (const int*)d_in[2];
    const float* X     = (const float*)d_in[3];
    const float* convW = (const float*)d_in[4];
    const float* W0    = (const float*)d_in[5];
    const float* Wg    = (const float*)d_in[6];
    const float* Ug    = (const float*)d_in[7];
    const float* lw    = (const float*)d_in[8];
    const float* lb    = (const float*)d_in[9];
    float* out = (float*)d_out;

    k_gather<<<S_STEPS, 256>>>(xind, X);
    k_prep<<<S_STEPS, 128>>>(eidx, etyp);
    k_zero<<<(S_STEPS * DIM + 255) / 256, 256>>>(out + (size_t)S_STEPS * VOUT);
    k_fragGX<<<1200, 256>>>();
    k_gemmA_mma<<<dim3(5, 30), 256>>>(Wg);
    k_gemmP0<<<dim3(5, 3, 5), 256>>>(convW, W0);
    k_recur<<<4, 320>>>(Ug);
    k_fragX1<<<40, 256>>>();
    k_logits_mma<<<(VOUT + 63) / 64, 256>>>(lw, lb, out);
    k_lse<<<S_STEPS, 256>>>(out);
    k_final<<<1600, 256>>>(out);
}